// round 3
// baseline (speedup 1.0000x reference)
#include <cuda_runtime.h>
#include <cstdint>

#define Hh 128
#define Ww 256
#define HW (Hh*Ww)
#define NB 4
#define CIN 256
#define Tc 64
#define CCLS 19

typedef unsigned long long u64;

// ---------------- packed f32x2 helpers (sm_100+) ----------------
__device__ __forceinline__ void fma2(u64& d, u64 a, u64 b) {
    asm("fma.rn.f32x2 %0, %1, %2, %0;" : "+l"(d) : "l"(a), "l"(b));
}
__device__ __forceinline__ u64 pack2(float x, float y) {
    u64 r; asm("mov.b64 %0, {%1, %2};" : "=l"(r) : "f"(x), "f"(y)); return r;
}
__device__ __forceinline__ float2 unpack2(u64 v) {
    float2 r; asm("mov.b64 {%0, %1}, %2;" : "=f"(r.x), "=f"(r.y) : "l"(v)); return r;
}

// ---------------- scratch (allocation-free: __device__ globals) ----------------
__device__ float g_y[NB * 128 * HW];    // concat(t1,t2): (4,128,128,256)  ~67MB
__device__ float g_x[NB * Tc * HW];     // after BN+ReLU: (4,64,128,256)   ~33MB
__device__ float g_flow[NB * 2 * HW];   // flow: (4,2,128,256)             ~1MB

// ============================================================================
// Kernel 1: both 1x1 convs (GEMM  C[64,32768] = W[64,256] * X[256,32768])
// block: 64 out-ch x 128 px, 256 threads, microtile 8ch x 4px, packed f32x2
// acc packed along channel pairs: acc2[4 ch-pairs][4 px]
// ============================================================================
__global__ void __launch_bounds__(256) k_conv1x1(
    const float* __restrict__ x1, const float* __restrict__ x2,
    const float* __restrict__ w1, const float* __restrict__ w2)
{
    __shared__ __align__(16) float Ws[32][64];    // [k][t]
    __shared__ __align__(16) float Xs[32][128];   // [k][p]

    const int pt = blockIdx.x;          // 0..255 pixel tile
    const int n  = blockIdx.y;          // batch
    const int wh = blockIdx.z;          // 0: t1 path, 1: t2 path

    const float* X  = (wh ? x2 : x1) + (size_t)n * CIN * HW + pt * 128;
    const float* Wg = wh ? w2 : w1;
    float* Y = g_y + (size_t)(n * 128 + wh * 64) * HW + pt * 128;

    const int tid = threadIdx.x;
    const int cb = (tid >> 5) * 8;      // channel base (warp-uniform)
    const int pb = (tid & 31) * 4;      // pixel base

    u64 acc2[4][4];
#pragma unroll
    for (int i = 0; i < 4; i++)
#pragma unroll
        for (int j = 0; j < 4; j++) acc2[i][j] = 0ull;

    for (int k0 = 0; k0 < 256; k0 += 32) {
        for (int i = tid; i < 2048; i += 256) {
            int t = i & 63, k = i >> 6;
            Ws[k][t] = Wg[t * CIN + k0 + k];
        }
        for (int i = tid; i < 4096; i += 256) {
            int k = i >> 7, p = i & 127;
            Xs[k][p] = X[(size_t)(k0 + k) * HW + p];
        }
        __syncthreads();
#pragma unroll
        for (int k = 0; k < 32; k++) {
            // 8 consecutive weight floats -> 4 packed ch-pairs
            ulonglong2 wa = *(const ulonglong2*)&Ws[k][cb];
            ulonglong2 wb = *(const ulonglong2*)&Ws[k][cb + 4];
            u64 w2v[4] = {wa.x, wa.y, wb.x, wb.y};
            float4 xv = *(const float4*)&Xs[k][pb];
            u64 xd[4] = {pack2(xv.x, xv.x), pack2(xv.y, xv.y),
                         pack2(xv.z, xv.z), pack2(xv.w, xv.w)};
#pragma unroll
            for (int i = 0; i < 4; i++)
#pragma unroll
                for (int j = 0; j < 4; j++) fma2(acc2[i][j], w2v[i], xd[j]);
        }
        __syncthreads();
    }
#pragma unroll
    for (int i = 0; i < 4; i++) {
        float2 v0 = unpack2(acc2[i][0]);
        float2 v1 = unpack2(acc2[i][1]);
        float2 v2 = unpack2(acc2[i][2]);
        float2 v3 = unpack2(acc2[i][3]);
        *(float4*)&Y[(size_t)(cb + 2 * i) * HW + pb]     = make_float4(v0.x, v1.x, v2.x, v3.x);
        *(float4*)&Y[(size_t)(cb + 2 * i + 1) * HW + pb] = make_float4(v0.y, v1.y, v2.y, v3.y);
    }
}

// ============================================================================
// Kernel 2: conv3x3 (128 -> 64, pad 1) + BN + ReLU, packed f32x2
// block tile: 64 out-ch x (16x16 px), 256 threads, microtile 8ch x 8px
// acc packed along channel pairs: acc2[4 ch-pairs][8 px]
// ============================================================================
__global__ void __launch_bounds__(256, 2) k_conv3x3_bn(
    const float* __restrict__ wf,
    const float* __restrict__ gamma, const float* __restrict__ beta,
    const float* __restrict__ mean,  const float* __restrict__ var)
{
    __shared__ __align__(16) float Xs[8 * 18 * 20];   // [cc][row(18)][col pad 20]
    __shared__ __align__(16) float Ws[8 * 9 * 64];    // [cc][tap][t]

    const int bx = blockIdx.x;          // 0..15 (W/16)
    const int by = blockIdx.y;          // 0..7  (H/16)
    const int n  = blockIdx.z;

    const int tid = threadIdx.x;
    const int cb  = (tid >> 5) * 8;     // channel octet (warp-uniform)
    const int g   = tid & 31;
    const int r   = g >> 1;             // 0..15 output row in tile
    const int hx  = (g & 1) * 8;        // 0 or 8: output col base

    u64 acc2[4][8];
#pragma unroll
    for (int i = 0; i < 4; i++)
#pragma unroll
        for (int j = 0; j < 8; j++) acc2[i][j] = 0ull;

    const float* Yb = g_y + (size_t)n * 128 * HW;

    for (int ch0 = 0; ch0 < 128; ch0 += 8) {
        // stage input halo tile 8 x 18 x 18
        for (int i = tid; i < 8 * 18 * 18; i += 256) {
            int cc = i / 324;
            int rem = i - cc * 324;
            int ry = rem / 18, rx = rem - (rem / 18) * 18;
            int gy = by * 16 + ry - 1;
            int gx = bx * 16 + rx - 1;
            float v = 0.f;
            if ((unsigned)gy < (unsigned)Hh && (unsigned)gx < (unsigned)Ww)
                v = Yb[(size_t)(ch0 + cc) * HW + gy * Ww + gx];
            Xs[cc * 360 + ry * 20 + rx] = v;
        }
        // stage weights as [cc][tap][t]
        for (int i = tid; i < 8 * 9 * 64; i += 256) {
            int t = i & 63;
            int tap = (i >> 6) % 9;
            int cc = i / 576;
            Ws[cc * 576 + tap * 64 + t] = wf[t * (128 * 9) + (ch0 + cc) * 9 + tap];
        }
        __syncthreads();

#pragma unroll
        for (int cc = 0; cc < 8; cc++) {
#pragma unroll
            for (int dy = 0; dy < 3; dy++) {
                const float* xp = &Xs[cc * 360 + (r + dy) * 20 + hx];
                float4 xa = *(const float4*)&xp[0];
                float4 xb = *(const float4*)&xp[4];
                float4 xc = *(const float4*)&xp[8];
                // hoisted pixel dups, shared across the 3 dx taps
                u64 xd[10];
                xd[0] = pack2(xa.x, xa.x); xd[1] = pack2(xa.y, xa.y);
                xd[2] = pack2(xa.z, xa.z); xd[3] = pack2(xa.w, xa.w);
                xd[4] = pack2(xb.x, xb.x); xd[5] = pack2(xb.y, xb.y);
                xd[6] = pack2(xb.z, xb.z); xd[7] = pack2(xb.w, xb.w);
                xd[8] = pack2(xc.x, xc.x); xd[9] = pack2(xc.y, xc.y);
#pragma unroll
                for (int dx = 0; dx < 3; dx++) {
                    const float* wp = &Ws[cc * 576 + (dy * 3 + dx) * 64 + cb];
                    ulonglong2 wa = *(const ulonglong2*)&wp[0];
                    ulonglong2 wb = *(const ulonglong2*)&wp[4];
                    u64 w2v[4] = {wa.x, wa.y, wb.x, wb.y};
#pragma unroll
                    for (int i = 0; i < 4; i++)
#pragma unroll
                        for (int j = 0; j < 8; j++)
                            fma2(acc2[i][j], w2v[i], xd[dx + j]);
                }
            }
        }
        __syncthreads();
    }

    // epilogue: BN + ReLU, store to g_x (unpack channel pairs)
    const int oy = by * 16 + r;
    const int ox = bx * 16 + hx;
#pragma unroll
    for (int i = 0; i < 4; i++) {
        int t0 = cb + 2 * i, t1 = t0 + 1;
        float s0 = gamma[t0] * rsqrtf(var[t0] + 1e-5f);
        float b0 = beta[t0] - mean[t0] * s0;
        float s1 = gamma[t1] * rsqrtf(var[t1] + 1e-5f);
        float b1 = beta[t1] - mean[t1] * s1;
        float o0[8], o1[8];
#pragma unroll
        for (int j = 0; j < 8; j++) {
            float2 v = unpack2(acc2[i][j]);
            float a0 = v.x * s0 + b0;
            float a1 = v.y * s1 + b1;
            o0[j] = a0 > 0.f ? a0 : 0.f;
            o1[j] = a1 > 0.f ? a1 : 0.f;
        }
        float* d0 = g_x + (size_t)((n * Tc + t0) * Hh + oy) * Ww + ox;
        float* d1 = g_x + (size_t)((n * Tc + t1) * Hh + oy) * Ww + ox;
        *(float4*)&d0[0] = make_float4(o0[0], o0[1], o0[2], o0[3]);
        *(float4*)&d0[4] = make_float4(o0[4], o0[5], o0[6], o0[7]);
        *(float4*)&d1[0] = make_float4(o1[0], o1[1], o1[2], o1[3]);
        *(float4*)&d1[4] = make_float4(o1[4], o1[5], o1[6], o1[7]);
    }
}

// ============================================================================
// Kernel 3: conv3x3 (64 -> 2, pad 1) -> flow
// ============================================================================
__global__ void __launch_bounds__(256) k_flowconv(const float* __restrict__ w2)
{
    __shared__ __align__(16) float Xs[8 * 10 * 36];   // [cc][row(10)][col(34) pad 36]
    __shared__ __align__(16) float Ws[2 * 64 * 9];

    const int bx = blockIdx.x;          // 0..7  (W/32)
    const int by = blockIdx.y;          // 0..15 (H/8)
    const int n  = blockIdx.z;

    const int tid = threadIdx.x;
    const int py = tid >> 5;            // 0..7
    const int px = tid & 31;            // 0..31

    for (int i = tid; i < 1152; i += 256) Ws[i] = w2[i];

    float a0 = 0.f, a1 = 0.f;
    const float* Xb = g_x + (size_t)n * Tc * HW;

    for (int c0 = 0; c0 < 64; c0 += 8) {
        for (int i = tid; i < 8 * 10 * 34; i += 256) {
            int cc = i / 340;
            int rem = i - cc * 340;
            int ry = rem / 34, rx = rem - (rem / 34) * 34;
            int gy = by * 8 + ry - 1;
            int gx = bx * 32 + rx - 1;
            float v = 0.f;
            if ((unsigned)gy < (unsigned)Hh && (unsigned)gx < (unsigned)Ww)
                v = Xb[(size_t)(c0 + cc) * HW + gy * Ww + gx];
            Xs[cc * 360 + ry * 36 + rx] = v;
        }
        __syncthreads();
#pragma unroll
        for (int cc = 0; cc < 8; cc++) {
            int c = c0 + cc;
#pragma unroll
            for (int dy = 0; dy < 3; dy++) {
#pragma unroll
                for (int dx = 0; dx < 3; dx++) {
                    float xv = Xs[cc * 360 + (py + dy) * 36 + (px + dx)];
                    int tap = dy * 3 + dx;
                    a0 += Ws[c * 9 + tap] * xv;
                    a1 += Ws[(64 + c) * 9 + tap] * xv;
                }
            }
        }
        __syncthreads();
    }

    const int oy = by * 8 + py, ox = bx * 32 + px;
    g_flow[((size_t)(n * 2 + 0) * Hh + oy) * Ww + ox] = a0;
    g_flow[((size_t)(n * 2 + 1) * Hh + oy) * Ww + ox] = a1;
}

// ============================================================================
// Kernel 4: flow_warp with torch repeat(c,1,1,1) batch-aliasing
// ============================================================================
__global__ void __launch_bounds__(256) k_warp(
    const float* __restrict__ pred, float* __restrict__ out)
{
    const int idx = blockIdx.x * 256 + threadIdx.x;
    const int x = idx & (Ww - 1);
    const int y = (idx >> 8) & (Hh - 1);
    const int t = idx >> 15;                          // n*19+ch, 0..75
    const int fb = t & 3;                             // (n*19+ch)%4

    const float fx = g_flow[((size_t)(fb * 2 + 0) * Hh + y) * Ww + x];
    const float fy = g_flow[((size_t)(fb * 2 + 1) * Hh + y) * Ww + x];

    const float gx = -1.f + 2.f * (float)x / (float)(Ww - 1);
    const float gy = -1.f + 2.f * (float)y / (float)(Hh - 1);
    const float sx = gx + fx / (float)Ww;
    const float sy = gy + fy / (float)Hh;
    const float ix = ((sx + 1.f) * (float)Ww - 1.f) * 0.5f;
    const float iy = ((sy + 1.f) * (float)Hh - 1.f) * 0.5f;

    const float x0f = floorf(ix), y0f = floorf(iy);
    const float wx = ix - x0f, wy = iy - y0f;
    const int x0 = (int)x0f, y0 = (int)y0f;

    const float* img = pred + (size_t)t * HW;
    auto samp = [&](int yy, int xx) -> float {
        return (xx >= 0 && xx < Ww && yy >= 0 && yy < Hh) ? img[yy * Ww + xx] : 0.f;
    };
    const float v00 = samp(y0, x0);
    const float v01 = samp(y0, x0 + 1);
    const float v10 = samp(y0 + 1, x0);
    const float v11 = samp(y0 + 1, x0 + 1);

    const float top = v00 * (1.f - wx) + v01 * wx;
    const float bot = v10 * (1.f - wx) + v11 * wx;
    out[idx] = top * (1.f - wy) + bot * wy;
}

// ============================================================================
// launch
// ============================================================================
extern "C" void kernel_launch(void* const* d_in, const int* in_sizes, int n_in,
                              void* d_out, int out_size)
{
    const float* t1_feature = (const float*)d_in[0];
    const float* t2_feature = (const float*)d_in[1];
    const float* t2_pred    = (const float*)d_in[2];
    const float* w_down1    = (const float*)d_in[3];
    const float* w_down2    = (const float*)d_in[4];
    const float* w_flow1    = (const float*)d_in[5];
    const float* bn_gamma   = (const float*)d_in[6];
    const float* bn_beta    = (const float*)d_in[7];
    const float* bn_mean    = (const float*)d_in[8];
    const float* bn_var     = (const float*)d_in[9];
    const float* w_flow2    = (const float*)d_in[10];
    float* out = (float*)d_out;

    k_conv1x1<<<dim3(256, NB, 2), 256>>>(t1_feature, t2_feature, w_down1, w_down2);
    k_conv3x3_bn<<<dim3(Ww / 16, Hh / 16, NB), 256>>>(w_flow1, bn_gamma, bn_beta,
                                                      bn_mean, bn_var);
    k_flowconv<<<dim3(Ww / 32, Hh / 8, NB), 256>>>(w_flow2);
    k_warp<<<(NB * CCLS * HW) / 256, 256>>>(t2_pred, out);
}

// round 5
// speedup vs baseline: 2.3915x; 2.3915x over previous
#include <cuda_runtime.h>
#include <cuda_bf16.h>
#include <cstdint>

#define Hh 128
#define Ww 256
#define HW (Hh*Ww)
#define NB 4
#define CIN 256
#define Tc 64
#define CCLS 19

// ---------------- scratch (allocation-free: __device__ globals) ----------------
__device__ uint32_t g_y[NB * HW * 128];   // concat(t1,t2) PIXEL-major [nb][pix][ch], packed bf16 hi|lo
__device__ float    g_x[NB * Tc * HW];    // after BN+ReLU, channel-major (for k3)
__device__ float    g_flow[NB * 2 * HW];  // flow
// weight fragments: [..][lane][4] u32 where 4 = {hi_j0, hi_j1, lo_j0, lo_j1}
__device__ uint32_t g_wd[2 * 16 * 8 * 32 * 4];   // 1x1 convs: [wh][ks16][nf8][lane][4]
__device__ uint32_t g_wf[9 * 8 * 8 * 32 * 4];    // 3x3 conv:  [tap][ks8][nf8][lane][4]
__device__ float    g_bns[64], g_bnb[64];        // folded BN scale/bias

// ---------------- helpers ----------------
__device__ __forceinline__ uint32_t split_pack(float v) {
    __nv_bfloat16 h = __float2bfloat16(v);
    float r = v - __bfloat162float(h);
    __nv_bfloat16 l = __float2bfloat16(r);
    return ((uint32_t)__bfloat16_as_ushort(h) << 16) | (uint32_t)__bfloat16_as_ushort(l);
}
// split two fp32 into bf16x2 hi-reg and lo-reg (element0 in lower half)
__device__ __forceinline__ void split2(float a, float b, uint32_t& hi, uint32_t& lo) {
    __nv_bfloat16 ha = __float2bfloat16(a), hb = __float2bfloat16(b);
    float ra = a - __bfloat162float(ha), rb = b - __bfloat162float(hb);
    __nv_bfloat16 la = __float2bfloat16(ra), lb = __float2bfloat16(rb);
    hi = (uint32_t)__bfloat16_as_ushort(ha) | ((uint32_t)__bfloat16_as_ushort(hb) << 16);
    lo = (uint32_t)__bfloat16_as_ushort(la) | ((uint32_t)__bfloat16_as_ushort(lb) << 16);
}
// from two packed hi|lo u32 (adjacent channels) build bf16x2 regs
__device__ __forceinline__ uint32_t hi2(uint2 v) { return (v.x >> 16) | (v.y & 0xffff0000u); }
__device__ __forceinline__ uint32_t lo2(uint2 v) { return (v.x & 0xffffu) | (v.y << 16); }

__device__ __forceinline__ void mma16816(float (&c)[4], const uint32_t (&a)[4],
                                         uint32_t b0, uint32_t b1) {
    asm volatile(
        "mma.sync.aligned.m16n8k16.row.col.f32.bf16.bf16.f32 "
        "{%0,%1,%2,%3},{%4,%5,%6,%7},{%8,%9},{%0,%1,%2,%3};"
        : "+f"(c[0]), "+f"(c[1]), "+f"(c[2]), "+f"(c[3])
        : "r"(a[0]), "r"(a[1]), "r"(a[2]), "r"(a[3]), "r"(b0), "r"(b1));
}

// ============================================================================
// k_prep: weights -> mma fragment order (hi/lo split), BN fold
// ============================================================================
__global__ void __launch_bounds__(256) k_prep(
    const float* __restrict__ w1, const float* __restrict__ w2,
    const float* __restrict__ wf,
    const float* __restrict__ gamma, const float* __restrict__ beta,
    const float* __restrict__ mean,  const float* __restrict__ var)
{
    int i = blockIdx.x * 256 + threadIdx.x;
    if (i < 64) {
        float s = gamma[i] * rsqrtf(var[i] + 1e-5f);
        g_bns[i] = s;
        g_bnb[i] = beta[i] - mean[i] * s;
    }
    if (i < 2 * 16 * 8 * 32 * 2) {           // 1x1 weights
        int j    = i & 1;
        int lane = (i >> 1) & 31;
        int nf   = (i >> 6) & 7;
        int ks   = (i >> 9) & 15;
        int wh   = i >> 13;
        int n   = nf * 8 + (lane >> 2);
        int ch0 = ks * 16 + (lane & 3) * 2 + j * 8;
        const float* w = wh ? w2 : w1;
        float w0 = w[n * CIN + ch0], w1v = w[n * CIN + ch0 + 1];
        uint32_t hi, lo; split2(w0, w1v, hi, lo);
        int base = (((wh * 16 + ks) * 8 + nf) * 32 + lane) * 4;
        g_wd[base + j] = hi;
        g_wd[base + 2 + j] = lo;
    }
    int m = i - 2 * 16 * 8 * 32 * 2;
    if (m >= 0 && m < 9 * 8 * 8 * 32 * 2) {  // 3x3 weights
        int j    = m & 1;
        int lane = (m >> 1) & 31;
        int nf   = (m >> 6) & 7;
        int ks   = (m >> 9) & 7;
        int tap  = m >> 12;
        int n   = nf * 8 + (lane >> 2);
        int ch0 = ks * 16 + (lane & 3) * 2 + j * 8;
        float w0 = wf[n * (128 * 9) + ch0 * 9 + tap];
        float w1v = wf[n * (128 * 9) + (ch0 + 1) * 9 + tap];
        uint32_t hi, lo; split2(w0, w1v, hi, lo);
        int base = (((tap * 8 + ks) * 8 + nf) * 32 + lane) * 4;
        g_wf[base + j] = hi;
        g_wf[base + 2 + j] = lo;
    }
}

// ============================================================================
// k1: both 1x1 convs via mma.sync bf16 3-pass.
// CTA = 128 px x 64 out-ch; warp = 16 px x 64 ch. A direct from fp32 gmem.
// ============================================================================
__global__ void __launch_bounds__(256) k1_mma(
    const float* __restrict__ x1, const float* __restrict__ x2)
{
    extern __shared__ uint4 sB[];            // 4096 uint4 = 64KB (all 16 ksteps)
    const int tid = threadIdx.x, lane = tid & 31, wm = tid >> 5;
    const int pt = blockIdx.x, nb = blockIdx.y, wh = blockIdx.z;
    const int kq = lane & 3, nr = lane >> 2;

    // stage fragment-ordered weights
    const uint4* wd4 = (const uint4*)g_wd + wh * 4096;
#pragma unroll
    for (int it = 0; it < 16; it++) sB[tid + it * 256] = wd4[tid + it * 256];
    __syncthreads();

    const float* X = (wh ? x2 : x1) + (size_t)nb * CIN * HW;
    const int pix0 = pt * 128 + wm * 16 + nr;
    const int pix1 = pix0 + 8;

    float acc[8][4];
#pragma unroll
    for (int f = 0; f < 8; f++)
#pragma unroll
        for (int q = 0; q < 4; q++) acc[f][q] = 0.f;

#pragma unroll 2
    for (int ks = 0; ks < 16; ks++) {
        const int ch0 = ks * 16 + 2 * kq;
        const float* Xc = X + (size_t)ch0 * HW;
        float f00 = Xc[pix0],            f01 = Xc[HW + pix0];
        float f08 = Xc[8 * HW + pix0],   f09 = Xc[9 * HW + pix0];
        float f10 = Xc[pix1],            f11 = Xc[HW + pix1];
        float f18 = Xc[8 * HW + pix1],   f19 = Xc[9 * HW + pix1];
        uint32_t Ahi[4], Alo[4];
        split2(f00, f01, Ahi[0], Alo[0]);
        split2(f10, f11, Ahi[1], Alo[1]);
        split2(f08, f09, Ahi[2], Alo[2]);
        split2(f18, f19, Ahi[3], Alo[3]);
#pragma unroll
        for (int nf = 0; nf < 8; nf++) {
            uint4 b = sB[(ks * 8 + nf) * 32 + lane];
            mma16816(acc[nf], Ahi, b.x, b.y);   // hi*hi
            mma16816(acc[nf], Ahi, b.z, b.w);   // hi*lo
            mma16816(acc[nf], Alo, b.x, b.y);   // lo*hi
        }
    }

    // epilogue: pack to g_y pixel-major [pix][ch]
    uint32_t* gy = g_y + (size_t)nb * HW * 128;
#pragma unroll
    for (int nf = 0; nf < 8; nf++) {
        int ch = wh * 64 + nf * 8 + 2 * kq;
        uint2 v0 = make_uint2(split_pack(acc[nf][0]), split_pack(acc[nf][1]));
        uint2 v1 = make_uint2(split_pack(acc[nf][2]), split_pack(acc[nf][3]));
        *(uint2*)&gy[(size_t)pix0 * 128 + ch] = v0;
        *(uint2*)&gy[(size_t)pix1 * 128 + ch] = v1;
    }
}

// ============================================================================
// k2: conv3x3 (128->64) + BN + ReLU via mma.sync bf16 3-pass.
// CTA = 128 px (half-row) x 64 ch; 9 taps = pixel-shifted accumulating GEMMs.
// A direct from g_y (pixel-major packed), B staged per tap into SMEM.
// ============================================================================
__global__ void __launch_bounds__(256) k2_mma()
{
    __shared__ uint4 sB[2048];               // 32KB: one tap of fragments
    const int tid = threadIdx.x, lane = tid & 31, wm = tid >> 5;
    const int y  = blockIdx.x >> 1;
    const int xb = (blockIdx.x & 1) * 128;
    const int nb = blockIdx.y;
    const int kq = lane & 3, nr = lane >> 2;

    float acc[8][4];
#pragma unroll
    for (int f = 0; f < 8; f++)
#pragma unroll
        for (int q = 0; q < 4; q++) acc[f][q] = 0.f;

    const uint32_t* gy = g_y + (size_t)nb * HW * 128;
    const uint4* wf4 = (const uint4*)g_wf;

    for (int tap = 0; tap < 9; tap++) {
        __syncthreads();
#pragma unroll
        for (int it = 0; it < 8; it++) sB[tid + it * 256] = wf4[tap * 2048 + tid + it * 256];
        __syncthreads();

        const int dy = tap / 3 - 1, dx = tap % 3 - 1;
        const int gyr = y + dy;
        const int gx0 = xb + wm * 16 + nr + dx;
        const int gx1 = gx0 + 8;
        const bool okY = (unsigned)gyr < (unsigned)Hh;
        const bool v0 = okY && (unsigned)gx0 < (unsigned)Ww;
        const bool v1 = okY && (unsigned)gx1 < (unsigned)Ww;
        const uint2* A0 = (const uint2*)(gy + ((size_t)gyr * Ww + gx0) * 128);
        const uint2* A1 = (const uint2*)(gy + ((size_t)gyr * Ww + gx1) * 128);

#pragma unroll
        for (int ks = 0; ks < 8; ks++) {
            uint2 q00 = make_uint2(0u, 0u), q01 = q00, q10 = q00, q11 = q00;
            if (v0) { q00 = A0[ks * 8 + kq]; q01 = A0[ks * 8 + kq + 4]; }
            if (v1) { q10 = A1[ks * 8 + kq]; q11 = A1[ks * 8 + kq + 4]; }
            uint32_t Ahi[4] = {hi2(q00), hi2(q10), hi2(q01), hi2(q11)};
            uint32_t Alo[4] = {lo2(q00), lo2(q10), lo2(q01), lo2(q11)};
#pragma unroll
            for (int nf = 0; nf < 8; nf++) {
                uint4 b = sB[(ks * 8 + nf) * 32 + lane];
                mma16816(acc[nf], Ahi, b.x, b.y);
                mma16816(acc[nf], Ahi, b.z, b.w);
                mma16816(acc[nf], Alo, b.x, b.y);
            }
        }
    }

    // epilogue: BN + ReLU -> g_x channel-major
    const int op0 = y * Ww + xb + wm * 16 + nr;
    const int op1 = op0 + 8;
    float* Xo = g_x + (size_t)nb * Tc * HW;
#pragma unroll
    for (int nf = 0; nf < 8; nf++) {
        int ch = nf * 8 + 2 * kq;
        float s0 = g_bns[ch], b0 = g_bnb[ch];
        float s1 = g_bns[ch + 1], b1 = g_bnb[ch + 1];
        float r00 = acc[nf][0] * s0 + b0; r00 = r00 > 0.f ? r00 : 0.f;
        float r01 = acc[nf][1] * s1 + b1; r01 = r01 > 0.f ? r01 : 0.f;
        float r10 = acc[nf][2] * s0 + b0; r10 = r10 > 0.f ? r10 : 0.f;
        float r11 = acc[nf][3] * s1 + b1; r11 = r11 > 0.f ? r11 : 0.f;
        Xo[(size_t)ch * HW + op0]       = r00;
        Xo[(size_t)(ch + 1) * HW + op0] = r01;
        Xo[(size_t)ch * HW + op1]       = r10;
        Xo[(size_t)(ch + 1) * HW + op1] = r11;
    }
}

// ============================================================================
// k3: conv3x3 (64 -> 2, pad 1) -> flow   (SIMT, small)
// ============================================================================
__global__ void __launch_bounds__(256) k_flowconv(const float* __restrict__ w2)
{
    __shared__ __align__(16) float Xs[8 * 10 * 36];
    __shared__ __align__(16) float Ws[2 * 64 * 9];

    const int bx = blockIdx.x, by = blockIdx.y, n = blockIdx.z;
    const int tid = threadIdx.x;
    const int py = tid >> 5, px = tid & 31;

    for (int i = tid; i < 1152; i += 256) Ws[i] = w2[i];

    float a0 = 0.f, a1 = 0.f;
    const float* Xb = g_x + (size_t)n * Tc * HW;

    for (int c0 = 0; c0 < 64; c0 += 8) {
        for (int i = tid; i < 8 * 10 * 34; i += 256) {
            int cc = i / 340;
            int rem = i - cc * 340;
            int ry = rem / 34, rx = rem - (rem / 34) * 34;
            int gy = by * 8 + ry - 1;
            int gx = bx * 32 + rx - 1;
            float v = 0.f;
            if ((unsigned)gy < (unsigned)Hh && (unsigned)gx < (unsigned)Ww)
                v = Xb[(size_t)(c0 + cc) * HW + gy * Ww + gx];
            Xs[cc * 360 + ry * 36 + rx] = v;
        }
        __syncthreads();
#pragma unroll
        for (int cc = 0; cc < 8; cc++) {
            int c = c0 + cc;
#pragma unroll
            for (int dy = 0; dy < 3; dy++) {
#pragma unroll
                for (int dx = 0; dx < 3; dx++) {
                    float xv = Xs[cc * 360 + (py + dy) * 36 + (px + dx)];
                    int tap = dy * 3 + dx;
                    a0 += Ws[c * 9 + tap] * xv;
                    a1 += Ws[(64 + c) * 9 + tap] * xv;
                }
            }
        }
        __syncthreads();
    }

    const int oy = by * 8 + py, ox = bx * 32 + px;
    g_flow[((size_t)(n * 2 + 0) * Hh + oy) * Ww + ox] = a0;
    g_flow[((size_t)(n * 2 + 1) * Hh + oy) * Ww + ox] = a1;
}

// ============================================================================
// k4: flow_warp (torch repeat(c,1,1,1) batch-aliasing)
// ============================================================================
__global__ void __launch_bounds__(256) k_warp(
    const float* __restrict__ pred, float* __restrict__ out)
{
    const int idx = blockIdx.x * 256 + threadIdx.x;
    const int x = idx & (Ww - 1);
    const int y = (idx >> 8) & (Hh - 1);
    const int t = idx >> 15;
    const int fb = t & 3;

    const float fx = g_flow[((size_t)(fb * 2 + 0) * Hh + y) * Ww + x];
    const float fy = g_flow[((size_t)(fb * 2 + 1) * Hh + y) * Ww + x];

    const float gx = -1.f + 2.f * (float)x / (float)(Ww - 1);
    const float gy = -1.f + 2.f * (float)y / (float)(Hh - 1);
    const float sx = gx + fx / (float)Ww;
    const float sy = gy + fy / (float)Hh;
    const float ix = ((sx + 1.f) * (float)Ww - 1.f) * 0.5f;
    const float iy = ((sy + 1.f) * (float)Hh - 1.f) * 0.5f;

    const float x0f = floorf(ix), y0f = floorf(iy);
    const float wx = ix - x0f, wy = iy - y0f;
    const int x0 = (int)x0f, y0 = (int)y0f;

    const float* img = pred + (size_t)t * HW;
    auto samp = [&](int yy, int xx) -> float {
        return (xx >= 0 && xx < Ww && yy >= 0 && yy < Hh) ? img[yy * Ww + xx] : 0.f;
    };
    const float v00 = samp(y0, x0);
    const float v01 = samp(y0, x0 + 1);
    const float v10 = samp(y0 + 1, x0);
    const float v11 = samp(y0 + 1, x0 + 1);

    const float top = v00 * (1.f - wx) + v01 * wx;
    const float bot = v10 * (1.f - wx) + v11 * wx;
    out[idx] = top * (1.f - wy) + bot * wy;
}

// ============================================================================
// launch
// ============================================================================
extern "C" void kernel_launch(void* const* d_in, const int* in_sizes, int n_in,
                              void* d_out, int out_size)
{
    const float* t1_feature = (const float*)d_in[0];
    const float* t2_feature = (const float*)d_in[1];
    const float* t2_pred    = (const float*)d_in[2];
    const float* w_down1    = (const float*)d_in[3];
    const float* w_down2    = (const float*)d_in[4];
    const float* w_flow1    = (const float*)d_in[5];
    const float* bn_gamma   = (const float*)d_in[6];
    const float* bn_beta    = (const float*)d_in[7];
    const float* bn_mean    = (const float*)d_in[8];
    const float* bn_var     = (const float*)d_in[9];
    const float* w_flow2    = (const float*)d_in[10];
    float* out = (float*)d_out;

    cudaFuncSetAttribute(k1_mma, cudaFuncAttributeMaxDynamicSharedMemorySize, 65536);

    k_prep<<<(2 * 16 * 8 * 32 * 2 + 9 * 8 * 8 * 32 * 2 + 255) / 256, 256>>>(
        w_down1, w_down2, w_flow1, bn_gamma, bn_beta, bn_mean, bn_var);
    k1_mma<<<dim3(256, NB, 2), 256, 65536>>>(t1_feature, t2_feature);
    k2_mma<<<dim3(256, NB), 256>>>();
    k_flowconv<<<dim3(Ww / 32, Hh / 8, NB), 256>>>(w_flow2);
    k_warp<<<(NB * CCLS * HW) / 256, 256>>>(t2_pred, out);
}